// round 9
// baseline (speedup 1.0000x reference)
#include <cuda_runtime.h>
#include <cuda_bf16.h>
#include <math.h>

// Problem constants
#define BB   8
#define SS   1024
#define EE   1024
#define HH   16
#define DD   64
#define MTOT (BB*SS)      // 8192
#define NEG_INF_F (-3.4028234663852886e38f)

// Scratch (device globals: allocation-free). Resolved DEVICE-SIDE via
// selectors so kernel_launch makes zero non-stream CUDA API calls for them.
__device__ float g_Q[MTOT*EE];
__device__ float g_K[MTOT*EE];
__device__ float g_V[MTOT*EE];
__device__ float g_A[MTOT*EE];

__device__ __forceinline__ float* selbuf(int sel, const void* ext) {
    switch (sel) {
        case 0: return g_Q;
        case 1: return g_K;
        case 2: return g_V;
        case 3: return g_A;
    }
    return (float*)ext;
}

// ---------------------------------------------------------------------------
// SGEMM (NT): C[m,n] = alpha * ( sum_k A[m,k]*B[n,k] + bias[n] )
// A: [M,K] row-major, B: [N,K] row-major (i.e. X @ W^T), bias: [N]
// Block tile 128x128, K-tile 8, 256 threads, 8x8 per thread.
// ---------------------------------------------------------------------------
#define GBM 128
#define GBN 128
#define GBK 8
#define GLD 132   // padded leading dim

__global__ __launch_bounds__(256, 2)
void gemm_nt_bias(const float* __restrict__ Aext, int Asel,
                  const float* __restrict__ B,
                  const float* __restrict__ bias,
                  float* __restrict__ Cext, int Csel,
                  int M, int N, int K, float alpha)
{
    const float* A = selbuf(Asel, Aext);
    float*       C = selbuf(Csel, Cext);

    __shared__ float As[GBK][GLD];
    __shared__ float Bs[GBK][GLD];

    const int tid  = threadIdx.x;
    const int tx   = tid & 15;
    const int ty   = tid >> 4;
    const int lrow = tid >> 1;        // 0..127
    const int lcol = (tid & 1) << 2;  // 0 or 4

    const float* Ap = A + (size_t)(blockIdx.y * GBM + lrow) * K + lcol;
    const float* Bp = B + (size_t)(blockIdx.x * GBN + lrow) * K + lcol;

    float acc[8][8];
#pragma unroll
    for (int i = 0; i < 8; i++)
#pragma unroll
        for (int j = 0; j < 8; j++) acc[i][j] = 0.f;

    for (int k0 = 0; k0 < K; k0 += GBK) {
        float4 av = *(const float4*)(Ap + k0);
        float4 bv = *(const float4*)(Bp + k0);
        __syncthreads();
        As[lcol+0][lrow] = av.x; As[lcol+1][lrow] = av.y;
        As[lcol+2][lrow] = av.z; As[lcol+3][lrow] = av.w;
        Bs[lcol+0][lrow] = bv.x; Bs[lcol+1][lrow] = bv.y;
        Bs[lcol+2][lrow] = bv.z; Bs[lcol+3][lrow] = bv.w;
        __syncthreads();
#pragma unroll
        for (int kk = 0; kk < GBK; kk++) {
            float a[8], b[8];
            *(float4*)(a)     = *(const float4*)&As[kk][ty*8];
            *(float4*)(a + 4) = *(const float4*)&As[kk][ty*8 + 4];
            *(float4*)(b)     = *(const float4*)&Bs[kk][tx*8];
            *(float4*)(b + 4) = *(const float4*)&Bs[kk][tx*8 + 4];
#pragma unroll
            for (int i = 0; i < 8; i++)
#pragma unroll
                for (int j = 0; j < 8; j++)
                    acc[i][j] = fmaf(a[i], b[j], acc[i][j]);
        }
    }

    const int col0 = blockIdx.x * GBN + tx * 8;
    float bvals[8];
    *(float4*)(bvals)     = *(const float4*)&bias[col0];
    *(float4*)(bvals + 4) = *(const float4*)&bias[col0 + 4];

#pragma unroll
    for (int i = 0; i < 8; i++) {
        const int row = blockIdx.y * GBM + ty * 8 + i;
        float4 o0, o1;
        o0.x = alpha * (acc[i][0] + bvals[0]);
        o0.y = alpha * (acc[i][1] + bvals[1]);
        o0.z = alpha * (acc[i][2] + bvals[2]);
        o0.w = alpha * (acc[i][3] + bvals[3]);
        o1.x = alpha * (acc[i][4] + bvals[4]);
        o1.y = alpha * (acc[i][5] + bvals[5]);
        o1.z = alpha * (acc[i][6] + bvals[6]);
        o1.w = alpha * (acc[i][7] + bvals[7]);
        *(float4*)&C[(size_t)row * N + col0]     = o0;
        *(float4*)&C[(size_t)row * N + col0 + 4] = o1;
    }
}

// ---------------------------------------------------------------------------
// Fused flash-attention (fp32), Br=Bc=64, D=64.
// Reads g_Q/g_K/g_V directly, writes g_A. scores = QK^T + bias + amask,
// padded keys -> NEG_INF (replace), online softmax, O = P@V (normalized).
// key_padding_mask arrives as int32 (bool widened by the harness).
// ---------------------------------------------------------------------------
#define QLD 68   // padded lds (16B aligned: 68*4 = 272)

__global__ __launch_bounds__(256, 2)
void flash_attn(const float* __restrict__ bias,
                const int* __restrict__ kpm,
                const float* __restrict__ amask)
{
    const float* Q  = g_Q;
    const float* Kb = g_K;
    const float* Vb = g_V;
    float*       O  = g_A;

    extern __shared__ float sm[];
    float* Qt = sm;                 // [64][QLD]  (d-major: Qt[d][r])
    float* Kt = Qt + 64 * QLD;      // [64][QLD]  (d-major: Kt[d][c])
    float* Vs = Kt + 64 * QLD;      // [64][64]   (c-major: Vs[c][d])
    float* Ps = Vs + 64 * 64;       // [64][QLD]  (r-major: Ps[r][c])
    float* km = Ps + 64 * QLD;      // [64]

    const int tid = threadIdx.x;
    const int tx  = tid & 15;
    const int ty  = tid >> 4;
    const int b   = blockIdx.z;
    const int h   = blockIdx.y;
    const int q0  = blockIdx.x << 6;

    // Load Q tile (transpose to d-major)
#pragma unroll
    for (int t = 0; t < 16; t++) {
        const int idx = tid + t * 256;
        const int r = idx >> 6, d = idx & 63;
        Qt[d * QLD + r] = Q[(size_t)((b << 10) + q0 + r) * EE + (h << 6) + d];
    }

    float m_[4], l_[4], acc[4][4];
#pragma unroll
    for (int i = 0; i < 4; i++) {
        m_[i] = NEG_INF_F; l_[i] = 0.f;
#pragma unroll
        for (int j = 0; j < 4; j++) acc[i][j] = 0.f;
    }

    const float* biasBase = bias + (size_t)((b * HH + h) * SS + q0) * SS;

    for (int kt = 0; kt < 16; kt++) {
        const int k0 = kt << 6;
        __syncthreads();   // protect Kt/Vs/Ps from previous iteration
#pragma unroll
        for (int t = 0; t < 16; t++) {
            const int idx = tid + t * 256;
            const int c = idx >> 6, d = idx & 63;
            const size_t g = (size_t)((b << 10) + k0 + c) * EE + (h << 6) + d;
            Kt[d * QLD + c] = Kb[g];
            Vs[c * 64  + d] = Vb[g];
        }
        if (tid < 64) km[tid] = (kpm[(b << 10) + k0 + tid] != 0) ? 1.f : 0.f;
        __syncthreads();

        // S = Q K^T (4x4 fragment per thread)
        float s[4][4];
#pragma unroll
        for (int i = 0; i < 4; i++)
#pragma unroll
            for (int j = 0; j < 4; j++) s[i][j] = 0.f;

#pragma unroll 16
        for (int d = 0; d < 64; d++) {
            float a0[4], b0[4];
            *(float4*)a0 = *(const float4*)&Qt[d * QLD + ty * 4];
            *(float4*)b0 = *(const float4*)&Kt[d * QLD + tx * 4];
#pragma unroll
            for (int i = 0; i < 4; i++)
#pragma unroll
                for (int j = 0; j < 4; j++)
                    s[i][j] = fmaf(a0[i], b0[j], s[i][j]);
        }

        // + attn_bias + attn_mask, then padding mask (replace with NEG_INF)
        float4 kmv = *(const float4*)&km[tx * 4];
        const float kmf[4] = {kmv.x, kmv.y, kmv.z, kmv.w};
#pragma unroll
        for (int i = 0; i < 4; i++) {
            const float* bp = biasBase + (size_t)(ty * 4 + i) * SS + k0 + tx * 4;
            float4 bb = *(const float4*)bp;
            const float* ap = amask + (size_t)(q0 + ty * 4 + i) * SS + k0 + tx * 4;
            float4 aa = *(const float4*)ap;
            s[i][0] += bb.x + aa.x;
            s[i][1] += bb.y + aa.y;
            s[i][2] += bb.z + aa.z;
            s[i][3] += bb.w + aa.w;
#pragma unroll
            for (int j = 0; j < 4; j++)
                if (kmf[j] != 0.f) s[i][j] = NEG_INF_F;
        }

        // online softmax update (row reductions across the 16 tx lanes)
#pragma unroll
        for (int i = 0; i < 4; i++) {
            float mx = fmaxf(fmaxf(s[i][0], s[i][1]), fmaxf(s[i][2], s[i][3]));
#pragma unroll
            for (int off = 1; off < 16; off <<= 1)
                mx = fmaxf(mx, __shfl_xor_sync(0xffffffffu, mx, off));
            const float mn = fmaxf(m_[i], mx);
            const float corr = __expf(m_[i] - mn);
            m_[i] = mn;
            float rs = 0.f;
#pragma unroll
            for (int j = 0; j < 4; j++) {
                const float p = __expf(s[i][j] - mn);
                s[i][j] = p;
                rs += p;
            }
#pragma unroll
            for (int off = 1; off < 16; off <<= 1)
                rs += __shfl_xor_sync(0xffffffffu, rs, off);
            l_[i] = l_[i] * corr + rs;
#pragma unroll
            for (int j = 0; j < 4; j++) acc[i][j] *= corr;
        }

        // stash P, then acc += P @ V
#pragma unroll
        for (int i = 0; i < 4; i++)
            *(float4*)&Ps[(ty * 4 + i) * QLD + tx * 4] =
                make_float4(s[i][0], s[i][1], s[i][2], s[i][3]);
        __syncthreads();

#pragma unroll 16
        for (int c = 0; c < 64; c++) {
            float b0[4];
            *(float4*)b0 = *(const float4*)&Vs[c * 64 + tx * 4];
#pragma unroll
            for (int i = 0; i < 4; i++) {
                const float p = Ps[(ty * 4 + i) * QLD + c];
#pragma unroll
                for (int j = 0; j < 4; j++)
                    acc[i][j] = fmaf(p, b0[j], acc[i][j]);
            }
        }
    }

    // normalize + store O[b, q, h, d]
#pragma unroll
    for (int i = 0; i < 4; i++) {
        const float inv = 1.f / l_[i];
        const int r = q0 + ty * 4 + i;
        float4 o = make_float4(acc[i][0] * inv, acc[i][1] * inv,
                               acc[i][2] * inv, acc[i][3] * inv);
        *(float4*)&O[(size_t)((b << 10) + r) * EE + (h << 6) + tx * 4] = o;
    }
}

// ---------------------------------------------------------------------------
// Launch
// ---------------------------------------------------------------------------
extern "C" void kernel_launch(void* const* d_in, const int* in_sizes, int n_in,
                              void* d_out, int out_size)
{
    const float* query     = (const float*)d_in[0];
    // d_in[1] (key), d_in[2] (value) unused: self_attention projects all from query
    const float* attn_bias = (const float*)d_in[3];
    const int*   kpm       = (const int*)d_in[4];     // bool widened to int32
    const float* amask     = (const float*)d_in[5];
    const float* Wq        = (const float*)d_in[9];
    const float* bq        = (const float*)d_in[10];
    const float* Wk        = (const float*)d_in[11];
    const float* bk        = (const float*)d_in[12];
    const float* Wv        = (const float*)d_in[13];
    const float* bv        = (const float*)d_in[14];
    const float* Wo        = (const float*)d_in[15];
    const float* bo        = (const float*)d_in[16];
    float*       out       = (float*)d_out;

    const float scaling = 0.125f;  // D^-0.5, D=64

    dim3 gGrid(EE / GBN, MTOT / GBM);  // (8, 64)
    // selectors: 0=g_Q, 1=g_K, 2=g_V, 3=g_A, -1=use external pointer
    gemm_nt_bias<<<gGrid, 256>>>(query, -1, Wq, bq, nullptr, 0, MTOT, EE, EE, scaling);
    gemm_nt_bias<<<gGrid, 256>>>(query, -1, Wk, bk, nullptr, 1, MTOT, EE, EE, 1.0f);
    gemm_nt_bias<<<gGrid, 256>>>(query, -1, Wv, bv, nullptr, 2, MTOT, EE, EE, 1.0f);

    const size_t SMEM = (size_t)(64 * QLD * 3 + 64 * 64 + 64) * sizeof(float);
    cudaFuncSetAttribute(flash_attn, cudaFuncAttributeMaxDynamicSharedMemorySize,
                         (int)SMEM);
    dim3 fGrid(SS / 64, HH, BB);       // (16, 16, 8)
    flash_attn<<<fGrid, 256, SMEM>>>(attn_bias, kpm, amask);

    gemm_nt_bias<<<gGrid, 256>>>(nullptr, 3, Wo, bo, out, -1, MTOT, EE, EE, 1.0f);
}

// round 10
// speedup vs baseline: 1.0011x; 1.0011x over previous
#include <cuda_runtime.h>
#include <cuda_bf16.h>
#include <math.h>

// Problem constants
#define BB   8
#define SS   1024
#define EE   1024
#define HH   16
#define DD   64
#define MTOT (BB*SS)      // 8192
#define NEG_INF_F (-3.4028234663852886e38f)

// Scratch (device globals: allocation-free). Resolved DEVICE-SIDE via
// selectors so kernel_launch makes zero non-stream CUDA API calls for them.
__device__ float g_Q[MTOT*EE];
__device__ float g_K[MTOT*EE];
__device__ float g_V[MTOT*EE];
__device__ float g_A[MTOT*EE];

__device__ __forceinline__ float* selbuf(int sel, const void* ext) {
    switch (sel) {
        case 0: return g_Q;
        case 1: return g_K;
        case 2: return g_V;
        case 3: return g_A;
    }
    return (float*)ext;
}

// ---------------------------------------------------------------------------
// SGEMM (NT): C[m,n] = alpha * ( sum_k A[m,k]*B[n,k] + bias[n] )
// A: [M,K] row-major, B: [N,K] row-major (i.e. X @ W^T), bias: [N]
// Block tile 128x128, K-tile 8, 256 threads, 8x8 per thread.
// ---------------------------------------------------------------------------
#define GBM 128
#define GBN 128
#define GBK 8
#define GLD 132   // padded leading dim

__global__ __launch_bounds__(256, 2)
void gemm_nt_bias(const float* __restrict__ Aext, int Asel,
                  const float* __restrict__ B,
                  const float* __restrict__ bias,
                  float* __restrict__ Cext, int Csel,
                  int M, int N, int K, float alpha)
{
    const float* A = selbuf(Asel, Aext);
    float*       C = selbuf(Csel, Cext);

    __shared__ float As[GBK][GLD];
    __shared__ float Bs[GBK][GLD];

    const int tid  = threadIdx.x;
    const int tx   = tid & 15;
    const int ty   = tid >> 4;
    const int lrow = tid >> 1;        // 0..127
    const int lcol = (tid & 1) << 2;  // 0 or 4

    const float* Ap = A + (size_t)(blockIdx.y * GBM + lrow) * K + lcol;
    const float* Bp = B + (size_t)(blockIdx.x * GBN + lrow) * K + lcol;

    float acc[8][8];
#pragma unroll
    for (int i = 0; i < 8; i++)
#pragma unroll
        for (int j = 0; j < 8; j++) acc[i][j] = 0.f;

    for (int k0 = 0; k0 < K; k0 += GBK) {
        float4 av = *(const float4*)(Ap + k0);
        float4 bv = *(const float4*)(Bp + k0);
        __syncthreads();
        As[lcol+0][lrow] = av.x; As[lcol+1][lrow] = av.y;
        As[lcol+2][lrow] = av.z; As[lcol+3][lrow] = av.w;
        Bs[lcol+0][lrow] = bv.x; Bs[lcol+1][lrow] = bv.y;
        Bs[lcol+2][lrow] = bv.z; Bs[lcol+3][lrow] = bv.w;
        __syncthreads();
#pragma unroll
        for (int kk = 0; kk < GBK; kk++) {
            float a[8], b[8];
            *(float4*)(a)     = *(const float4*)&As[kk][ty*8];
            *(float4*)(a + 4) = *(const float4*)&As[kk][ty*8 + 4];
            *(float4*)(b)     = *(const float4*)&Bs[kk][tx*8];
            *(float4*)(b + 4) = *(const float4*)&Bs[kk][tx*8 + 4];
#pragma unroll
            for (int i = 0; i < 8; i++)
#pragma unroll
                for (int j = 0; j < 8; j++)
                    acc[i][j] = fmaf(a[i], b[j], acc[i][j]);
        }
    }

    const int col0 = blockIdx.x * GBN + tx * 8;
    float bvals[8];
    *(float4*)(bvals)     = *(const float4*)&bias[col0];
    *(float4*)(bvals + 4) = *(const float4*)&bias[col0 + 4];

#pragma unroll
    for (int i = 0; i < 8; i++) {
        const int row = blockIdx.y * GBM + ty * 8 + i;
        float4 o0, o1;
        o0.x = alpha * (acc[i][0] + bvals[0]);
        o0.y = alpha * (acc[i][1] + bvals[1]);
        o0.z = alpha * (acc[i][2] + bvals[2]);
        o0.w = alpha * (acc[i][3] + bvals[3]);
        o1.x = alpha * (acc[i][4] + bvals[4]);
        o1.y = alpha * (acc[i][5] + bvals[5]);
        o1.z = alpha * (acc[i][6] + bvals[6]);
        o1.w = alpha * (acc[i][7] + bvals[7]);
        *(float4*)&C[(size_t)row * N + col0]     = o0;
        *(float4*)&C[(size_t)row * N + col0 + 4] = o1;
    }
}

// ---------------------------------------------------------------------------
// Fused flash-attention (fp32), Br=Bc=64, D=64.
// Reads g_Q/g_K/g_V directly, writes g_A. scores = QK^T + bias + amask,
// padded keys -> NEG_INF (replace), online softmax, O = P@V (normalized).
// key_padding_mask arrives as int32 (bool widened by the harness).
// ---------------------------------------------------------------------------
#define QLD 68   // padded lds (16B aligned: 68*4 = 272)

__global__ __launch_bounds__(256, 2)
void flash_attn(const float* __restrict__ bias,
                const int* __restrict__ kpm,
                const float* __restrict__ amask)
{
    const float* Q  = g_Q;
    const float* Kb = g_K;
    const float* Vb = g_V;
    float*       O  = g_A;

    extern __shared__ float sm[];
    float* Qt = sm;                 // [64][QLD]  (d-major: Qt[d][r])
    float* Kt = Qt + 64 * QLD;      // [64][QLD]  (d-major: Kt[d][c])
    float* Vs = Kt + 64 * QLD;      // [64][64]   (c-major: Vs[c][d])
    float* Ps = Vs + 64 * 64;       // [64][QLD]  (r-major: Ps[r][c])
    float* km = Ps + 64 * QLD;      // [64]

    const int tid = threadIdx.x;
    const int tx  = tid & 15;
    const int ty  = tid >> 4;
    const int b   = blockIdx.z;
    const int h   = blockIdx.y;
    const int q0  = blockIdx.x << 6;

    // Load Q tile (transpose to d-major)
#pragma unroll
    for (int t = 0; t < 16; t++) {
        const int idx = tid + t * 256;
        const int r = idx >> 6, d = idx & 63;
        Qt[d * QLD + r] = Q[(size_t)((b << 10) + q0 + r) * EE + (h << 6) + d];
    }

    float m_[4], l_[4], acc[4][4];
#pragma unroll
    for (int i = 0; i < 4; i++) {
        m_[i] = NEG_INF_F; l_[i] = 0.f;
#pragma unroll
        for (int j = 0; j < 4; j++) acc[i][j] = 0.f;
    }

    const float* biasBase = bias + (size_t)((b * HH + h) * SS + q0) * SS;

    for (int kt = 0; kt < 16; kt++) {
        const int k0 = kt << 6;
        __syncthreads();   // protect Kt/Vs/Ps from previous iteration
#pragma unroll
        for (int t = 0; t < 16; t++) {
            const int idx = tid + t * 256;
            const int c = idx >> 6, d = idx & 63;
            const size_t g = (size_t)((b << 10) + k0 + c) * EE + (h << 6) + d;
            Kt[d * QLD + c] = Kb[g];
            Vs[c * 64  + d] = Vb[g];
        }
        if (tid < 64) km[tid] = (kpm[(b << 10) + k0 + tid] != 0) ? 1.f : 0.f;
        __syncthreads();

        // S = Q K^T (4x4 fragment per thread)
        float s[4][4];
#pragma unroll
        for (int i = 0; i < 4; i++)
#pragma unroll
            for (int j = 0; j < 4; j++) s[i][j] = 0.f;

#pragma unroll 16
        for (int d = 0; d < 64; d++) {
            float a0[4], b0[4];
            *(float4*)a0 = *(const float4*)&Qt[d * QLD + ty * 4];
            *(float4*)b0 = *(const float4*)&Kt[d * QLD + tx * 4];
#pragma unroll
            for (int i = 0; i < 4; i++)
#pragma unroll
                for (int j = 0; j < 4; j++)
                    s[i][j] = fmaf(a0[i], b0[j], s[i][j]);
        }

        // + attn_bias + attn_mask, then padding mask (replace with NEG_INF)
        float4 kmv = *(const float4*)&km[tx * 4];
        const float kmf[4] = {kmv.x, kmv.y, kmv.z, kmv.w};
#pragma unroll
        for (int i = 0; i < 4; i++) {
            const float* bp = biasBase + (size_t)(ty * 4 + i) * SS + k0 + tx * 4;
            float4 bb = *(const float4*)bp;
            const float* ap = amask + (size_t)(q0 + ty * 4 + i) * SS + k0 + tx * 4;
            float4 aa = *(const float4*)ap;
            s[i][0] += bb.x + aa.x;
            s[i][1] += bb.y + aa.y;
            s[i][2] += bb.z + aa.z;
            s[i][3] += bb.w + aa.w;
#pragma unroll
            for (int j = 0; j < 4; j++)
                if (kmf[j] != 0.f) s[i][j] = NEG_INF_F;
        }

        // online softmax update (row reductions across the 16 tx lanes)
#pragma unroll
        for (int i = 0; i < 4; i++) {
            float mx = fmaxf(fmaxf(s[i][0], s[i][1]), fmaxf(s[i][2], s[i][3]));
#pragma unroll
            for (int off = 1; off < 16; off <<= 1)
                mx = fmaxf(mx, __shfl_xor_sync(0xffffffffu, mx, off));
            const float mn = fmaxf(m_[i], mx);
            const float corr = __expf(m_[i] - mn);
            m_[i] = mn;
            float rs = 0.f;
#pragma unroll
            for (int j = 0; j < 4; j++) {
                const float p = __expf(s[i][j] - mn);
                s[i][j] = p;
                rs += p;
            }
#pragma unroll
            for (int off = 1; off < 16; off <<= 1)
                rs += __shfl_xor_sync(0xffffffffu, rs, off);
            l_[i] = l_[i] * corr + rs;
#pragma unroll
            for (int j = 0; j < 4; j++) acc[i][j] *= corr;
        }

        // stash P, then acc += P @ V
#pragma unroll
        for (int i = 0; i < 4; i++)
            *(float4*)&Ps[(ty * 4 + i) * QLD + tx * 4] =
                make_float4(s[i][0], s[i][1], s[i][2], s[i][3]);
        __syncthreads();

#pragma unroll 16
        for (int c = 0; c < 64; c++) {
            float b0[4];
            *(float4*)b0 = *(const float4*)&Vs[c * 64 + tx * 4];
#pragma unroll
            for (int i = 0; i < 4; i++) {
                const float p = Ps[(ty * 4 + i) * QLD + c];
#pragma unroll
                for (int j = 0; j < 4; j++)
                    acc[i][j] = fmaf(p, b0[j], acc[i][j]);
            }
        }
    }

    // normalize + store O[b, q, h, d]
#pragma unroll
    for (int i = 0; i < 4; i++) {
        const float inv = 1.f / l_[i];
        const int r = q0 + ty * 4 + i;
        float4 o = make_float4(acc[i][0] * inv, acc[i][1] * inv,
                               acc[i][2] * inv, acc[i][3] * inv);
        *(float4*)&O[(size_t)((b << 10) + r) * EE + (h << 6) + tx * 4] = o;
    }
}

// ---------------------------------------------------------------------------
// Launch
// ---------------------------------------------------------------------------
extern "C" void kernel_launch(void* const* d_in, const int* in_sizes, int n_in,
                              void* d_out, int out_size)
{
    const float* query     = (const float*)d_in[0];
    // d_in[1] (key), d_in[2] (value) unused: self_attention projects all from query
    const float* attn_bias = (const float*)d_in[3];
    const int*   kpm       = (const int*)d_in[4];     // bool widened to int32
    const float* amask     = (const float*)d_in[5];
    const float* Wq        = (const float*)d_in[9];
    const float* bq        = (const float*)d_in[10];
    const float* Wk        = (const float*)d_in[11];
    const float* bk        = (const float*)d_in[12];
    const float* Wv        = (const float*)d_in[13];
    const float* bv        = (const float*)d_in[14];
    const float* Wo        = (const float*)d_in[15];
    const float* bo        = (const float*)d_in[16];
    float*       out       = (float*)d_out;

    const float scaling = 0.125f;  // D^-0.5, D=64

    dim3 gGrid(EE / GBN, MTOT / GBM);  // (8, 64)
    // selectors: 0=g_Q, 1=g_K, 2=g_V, 3=g_A, -1=use external pointer
    gemm_nt_bias<<<gGrid, 256>>>(query, -1, Wq, bq, nullptr, 0, MTOT, EE, EE, scaling);
    gemm_nt_bias<<<gGrid, 256>>>(query, -1, Wk, bk, nullptr, 1, MTOT, EE, EE, 1.0f);
    gemm_nt_bias<<<gGrid, 256>>>(query, -1, Wv, bv, nullptr, 2, MTOT, EE, EE, 1.0f);

    const size_t SMEM = (size_t)(64 * QLD * 3 + 64 * 64 + 64) * sizeof(float);
    cudaFuncSetAttribute(flash_attn, cudaFuncAttributeMaxDynamicSharedMemorySize,
                         (int)SMEM);
    dim3 fGrid(SS / 64, HH, BB);       // (16, 16, 8)
    flash_attn<<<fGrid, 256, SMEM>>>(attn_bias, kpm, amask);

    gemm_nt_bias<<<gGrid, 256>>>(nullptr, 3, Wo, bo, out, -1, MTOT, EE, EE, 1.0f);
}